// round 9
// baseline (speedup 1.0000x reference)
#include <cuda_runtime.h>

// ---------------------------------------------------------------------------
// DummyGCN4: 4-layer GCN, output = h3[node 1] only.
// R9: ONE full-edge pass builds a per-node in-edge LINKED LIST
//     (head[d] = e+1, next[e] = previous head; 0 = end). All backward
//     expansions become direct chain walks (node 1 -> B2 -> B1 -> B0),
//     eliminating the 3 extra full scans that dominated R2 (4 x ~8.5us).
//     head is zero-init-friendly (e+1 encoding) and reset by k_h1x2 each
//     call; bitmaps/counters reset by k_tail via captured lists.
// ---------------------------------------------------------------------------

#define MAXN 50048
#define BMW  1568
#define OUT_NODE 1
#define NEXTCAP 1000000   // >= E
#define E1CAP  8192       // in-degree of node 1 (expect ~16)
#define E2CAP  32768      // edges into B2 (expect ~256)
#define EBCAP  262144     // edges into B1 (expect ~4k)

__device__ int   g_head[MAXN];        // e+1; 0 = empty. MUST be 0 at call start.
__device__ int   g_next[NEXTCAP];
__device__ unsigned g_B0[BMW], g_B1[BMW], g_B2[BMW];
__device__ int   g_list0[MAXN], g_list1[MAXN], g_list2[MAXN];
__device__ int   g_cnt0, g_cnt1, g_cnt2;
__device__ int   g_e1s[E1CAP];                 __device__ int g_e1n;
__device__ int   g_e2s[E2CAP],  g_e2d[E2CAP];  __device__ int g_e2n;
__device__ int   g_ebs[EBCAP],  g_ebd[EBCAP];  __device__ int g_ebn;
__device__ float g_agg0[MAXN];
__device__ float g_agg1[(size_t)MAXN * 64];
__device__ float g_x2[(size_t)MAXN * 64];
__device__ float g_agg2[(size_t)MAXN * 64];
__device__ float g_x3[MAXN];

__device__ __forceinline__ float lrelu(float x) { return x >= 0.f ? x : 0.01f * x; }
__device__ __forceinline__ void zero64(float* a) {
    float4 z = make_float4(0.f, 0.f, 0.f, 0.f);
    float4* a4 = (float4*)a;
    #pragma unroll
    for (int j = 0; j < 16; j++) a4[j] = z;
}

// ---------------- build: ONE full pass, per-dst in-edge linked lists --------
__global__ void k_build(const int* __restrict__ dst, int E) {
    int t = blockIdx.x * blockDim.x + threadIdx.x;
    int base = t * 4;
    if (base + 3 < E) {
        int4 d4 = __ldg((const int4*)(dst + base));
        g_next[base + 0] = atomicExch(&g_head[d4.x], base + 1);
        g_next[base + 1] = atomicExch(&g_head[d4.y], base + 2);
        g_next[base + 2] = atomicExch(&g_head[d4.z], base + 3);
        g_next[base + 3] = atomicExch(&g_head[d4.w], base + 4);
    } else {
        for (int e = base; e < E; e++)
            g_next[e] = atomicExch(&g_head[__ldg(&dst[e])], e + 1);
    }
}

// ---------------- t2: walk node-1 chain -> e1 srcs, B2/list2 ----------------
__global__ void k_t2(const int* __restrict__ src) {
    if (threadIdx.x != 0) return;
    int h = g_head[OUT_NODE];
    int n1 = 0, n2 = 0;
    while (h && n1 < E1CAP) {
        int e = h - 1;
        int s = __ldg(&src[e]);
        g_e1s[n1++] = s;
        unsigned m = 1u << (s & 31);
        unsigned old = atomicOr(&g_B2[s >> 5], m);
        if (!(old & m)) { g_list2[n2++] = s; zero64(&g_agg2[(size_t)s * 64]); }
        h = g_next[e];
    }
    g_e1n = n1; g_cnt2 = n2;
}

// ---------------- t21: chains of B2 nodes -> e2, B1/list1 ----------------
__global__ void k_t21(const int* __restrict__ src) {
    int n = g_cnt2;
    int NT = gridDim.x * blockDim.x;
    for (int i = blockIdx.x * blockDim.x + threadIdx.x; i < n; i += NT) {
        int v = g_list2[i];
        int h = g_head[v];
        while (h) {
            int e = h - 1;
            int s = __ldg(&src[e]);
            int p = atomicAdd(&g_e2n, 1);
            if (p < E2CAP) { g_e2s[p] = s; g_e2d[p] = v; }
            unsigned m = 1u << (s & 31);
            unsigned old = atomicOr(&g_B1[s >> 5], m);
            if (!(old & m)) {
                int q = atomicAdd(&g_cnt1, 1);
                g_list1[q] = s;
                zero64(&g_agg1[(size_t)s * 64]);
            }
            h = g_next[e];
        }
    }
}

// ---------------- t10: chains of B1 nodes -> eb, B0/list0 ----------------
__global__ void k_t10(const int* __restrict__ src) {
    int n = g_cnt1;
    int NT = gridDim.x * blockDim.x;
    for (int i = blockIdx.x * blockDim.x + threadIdx.x; i < n; i += NT) {
        int v = g_list1[i];
        int h = g_head[v];
        while (h) {
            int e = h - 1;
            int s = __ldg(&src[e]);
            int p = atomicAdd(&g_ebn, 1);
            if (p < EBCAP) { g_ebs[p] = s; g_ebd[p] = v; }
            unsigned m = 1u << (s & 31);
            unsigned old = atomicOr(&g_B0[s >> 5], m);
            if (!(old & m)) {
                int q = atomicAdd(&g_cnt0, 1);
                g_list0[q] = s;
            }
            h = g_next[e];
        }
    }
}

// ---------------- agg0: thread per B0 node, walk chain, plain store ---------
__global__ void k_agg0(const int* __restrict__ src, const float* __restrict__ in_feat) {
    int n = g_cnt0;
    int NT = gridDim.x * blockDim.x;
    for (int i = blockIdx.x * blockDim.x + threadIdx.x; i < n; i += NT) {
        int v = g_list0[i];
        float sum = 0.f;
        int h = g_head[v];
        while (h) {
            int e = h - 1;
            sum += __ldg(&in_feat[__ldg(&src[e])]);
            h = g_next[e];
        }
        g_agg0[v] = sum;
    }
}

// ---------------- agg1: agg1[d][:] += lrelu(agg0[s]*W0+b0), warp/edge -------
__global__ void k_agg1(const float* __restrict__ W0, const float* __restrict__ b0) {
    int n = min(g_ebn, EBCAP);
    int lane = threadIdx.x & 31;
    int warp = (blockIdx.x * blockDim.x + threadIdx.x) >> 5;
    int nw = (gridDim.x * blockDim.x) >> 5;
    float w0a = __ldg(&W0[lane]), w0b = __ldg(&W0[lane + 32]);
    float b0a = __ldg(&b0[lane]), b0b = __ldg(&b0[lane + 32]);
    for (int i = warp; i < n; i += nw) {
        int s = g_ebs[i], d = g_ebd[i];
        float a0 = g_agg0[s];
        float* a = &g_agg1[(size_t)d * 64];
        atomicAdd(&a[lane],      lrelu(fmaf(a0, w0a, b0a)));
        atomicAdd(&a[lane + 32], lrelu(fmaf(a0, w0b, b0b)));
    }
}

// ---------------- h1x2: per node in list1 (warp/node) + head reset ----------
__global__ void k_h1x2(const float* __restrict__ W1, const float* __restrict__ b1,
                       const float* __restrict__ W2) {
    int n = g_cnt1;
    int lane = threadIdx.x & 31;
    int tid = blockIdx.x * blockDim.x + threadIdx.x;
    int NT = gridDim.x * blockDim.x;
    int warp = tid >> 5;
    int nw = NT >> 5;
    for (int i = warp; i < n; i += nw) {
        int v = g_list1[i];
        float a0 = g_agg1[(size_t)v * 64 + lane];
        float a1 = g_agg1[(size_t)v * 64 + lane + 32];
        float h0r = __ldg(&b1[lane]);
        float h1r = __ldg(&b1[lane + 32]);
        float h2r = __ldg(&b1[lane + 64]);
        float h3r = __ldg(&b1[lane + 96]);
        #pragma unroll
        for (int k = 0; k < 64; k++) {
            float ak = __shfl_sync(0xffffffffu, (k < 32) ? a0 : a1, k & 31);
            const float* wr = &W1[k * 128];
            h0r = fmaf(ak, __ldg(&wr[lane]),      h0r);
            h1r = fmaf(ak, __ldg(&wr[lane + 32]), h1r);
            h2r = fmaf(ak, __ldg(&wr[lane + 64]), h2r);
            h3r = fmaf(ak, __ldg(&wr[lane + 96]), h3r);
        }
        float h[4] = { lrelu(h0r), lrelu(h1r), lrelu(h2r), lrelu(h3r) };
        float x0 = 0.f, x1 = 0.f;
        #pragma unroll
        for (int k = 0; k < 128; k++) {
            float hk = __shfl_sync(0xffffffffu, h[k >> 5], k & 31);
            const float* wr = &W2[k * 64];
            x0 = fmaf(hk, __ldg(&wr[lane]),      x0);
            x1 = fmaf(hk, __ldg(&wr[lane + 32]), x1);
        }
        g_x2[(size_t)v * 64 + lane]      = x0;
        g_x2[(size_t)v * 64 + lane + 32] = x1;
    }
    // reset head for next call (chains no longer needed after k_agg0)
    for (int i = tid; i < MAXN; i += NT) g_head[i] = 0;
}

// ---------------- tail: agg2 + h2x3 + final + out + cleanup (1 block) -------
__global__ void __launch_bounds__(1024, 1)
k_tail(const float* __restrict__ b2, const float* __restrict__ W3,
       const float* __restrict__ b3, float* __restrict__ out) {
    int lane = threadIdx.x & 31;
    int bw = threadIdx.x >> 5;

    int n2 = min(g_e2n, E2CAP);
    for (int i = bw; i < n2; i += 32) {
        int s = g_e2s[i], d = g_e2d[i];
        float* a = &g_agg2[(size_t)d * 64];
        atomicAdd(&a[lane],      __ldcg(&g_x2[(size_t)s * 64 + lane]));
        atomicAdd(&a[lane + 32], __ldcg(&g_x2[(size_t)s * 64 + lane + 32]));
    }
    __syncthreads();

    int n3 = g_cnt2;
    for (int i = bw; i < n3; i += 32) {
        int v = g_list2[i];
        float ya = lrelu(__ldcg(&g_agg2[(size_t)v * 64 + lane])      + __ldg(&b2[lane]));
        float yb = lrelu(__ldcg(&g_agg2[(size_t)v * 64 + lane + 32]) + __ldg(&b2[lane + 32]));
        float p = fmaf(ya, __ldg(&W3[lane]), yb * __ldg(&W3[lane + 32]));
        #pragma unroll
        for (int o = 16; o; o >>= 1) p += __shfl_down_sync(0xffffffffu, p, o);
        if (lane == 0) g_x3[v] = p;
    }
    __syncthreads();

    __shared__ float red[32];
    int n1 = min(g_e1n, E1CAP);
    float s = 0.f;
    for (int i = threadIdx.x; i < n1; i += 1024) s += __ldcg(&g_x3[g_e1s[i]]);
    #pragma unroll
    for (int o = 16; o; o >>= 1) s += __shfl_down_sync(0xffffffffu, s, o);
    if (lane == 0) red[bw] = s;
    __syncthreads();
    if (threadIdx.x < 32) {
        float t = red[lane];
        #pragma unroll
        for (int o = 16; o; o >>= 1) t += __shfl_down_sync(0xffffffffu, t, o);
        if (lane == 0) out[0] = lrelu(t + __ldg(&b3[0]));
    }
    __syncthreads();

    // cleanup: bitmaps via captured lists, then counters
    int c2 = g_cnt2, c1 = g_cnt1, c0 = g_cnt0;
    for (int i = threadIdx.x; i < c2; i += 1024) { int v = g_list2[i]; g_B2[v >> 5] = 0u; }
    for (int i = threadIdx.x; i < c1; i += 1024) { int v = g_list1[i]; g_B1[v >> 5] = 0u; }
    for (int i = threadIdx.x; i < c0; i += 1024) { int v = g_list0[i]; g_B0[v >> 5] = 0u; }
    __syncthreads();
    if (threadIdx.x == 0) {
        g_cnt0 = 0; g_cnt1 = 0; g_cnt2 = 0; g_e1n = 0; g_e2n = 0; g_ebn = 0;
        __threadfence();
    }
}

// ---------------------------------------------------------------------------
extern "C" void kernel_launch(void* const* d_in, const int* in_sizes, int n_in,
                              void* d_out, int out_size) {
    const float* in_feat = (const float*)d_in[0];
    const int*   src     = (const int*)  d_in[1];
    const int*   dst     = (const int*)  d_in[2];
    const float* W0 = (const float*)d_in[3];
    const float* b0 = (const float*)d_in[4];
    const float* W1 = (const float*)d_in[5];
    const float* b1 = (const float*)d_in[6];
    const float* W2 = (const float*)d_in[7];
    const float* b2 = (const float*)d_in[8];
    const float* W3 = (const float*)d_in[9];
    const float* b3 = (const float*)d_in[10];
    float* out = (float*)d_out;

    int E = in_sizes[1];
    int T = (E + 3) / 4;
    int bb = (T + 255) / 256;            // ~782 blocks

    k_build<<<bb, 256>>>(dst, E);        // the ONLY full-edge pass
    k_t2<<<1, 32>>>(src);
    k_t21<<<1, 128>>>(src);
    k_t10<<<2, 256>>>(src);
    k_agg0<<<32, 256>>>(src, in_feat);
    k_agg1<<<128, 256>>>(W0, b0);
    k_h1x2<<<64, 256>>>(W1, b1, W2);
    k_tail<<<1, 1024>>>(b2, W3, b3, out);
}

// round 10
// speedup vs baseline: 1.9944x; 1.9944x over previous
#include <cuda_runtime.h>

// ---------------------------------------------------------------------------
// DummyGCN4: 4-layer GCN, output = h3[node 1] only.
// R10: ONE full edge pass builds fixed-slot in-edge buckets:
//        p = atomicAdd(&deg[d],1); bucket_src[d*64+p] = src
//      (dst ~ Poisson(16) over 50k nodes; P(deg>=64) ~ 1e-17, and guarded).
//      All backward expansions become coalesced bucket-segment reads — no
//      pointer chasing (R9's failure), no extra full scans (R2's cost).
//      deg/bitmaps/counters reset at the end of k_tail for graph replay.
// ---------------------------------------------------------------------------

#define MAXN 50048
#define BCAP 64
#define BMW  1568
#define OUT_NODE 1
#define E2CAP  32768
#define EBCAP  262144

__device__ int   g_deg[MAXN];                       // zero-init; reset by k_tail
__device__ int   g_bucket[(size_t)MAXN * BCAP];
__device__ unsigned g_B0[BMW], g_B1[BMW], g_B2[BMW];
__device__ int   g_list0[MAXN], g_list1[MAXN], g_list2[MAXN];
__device__ int   g_cnt0, g_cnt1, g_cnt2;
__device__ int   g_e2s[E2CAP],  g_e2d[E2CAP];  __device__ int g_e2n;
__device__ int   g_ebs[EBCAP],  g_ebd[EBCAP];  __device__ int g_ebn;
__device__ float g_agg0[MAXN];
__device__ float g_agg1[(size_t)MAXN * 64];
__device__ float g_x2[(size_t)MAXN * 64];
__device__ float g_agg2[(size_t)MAXN * 64];
__device__ float g_x3[MAXN];

__device__ __forceinline__ float lrelu(float x) { return x >= 0.f ? x : 0.01f * x; }
__device__ __forceinline__ void zero64(float* a) {
    float4 z = make_float4(0.f, 0.f, 0.f, 0.f);
    float4* a4 = (float4*)a;
    #pragma unroll
    for (int j = 0; j < 16; j++) a4[j] = z;
}

// ---------------- k_bucket: the ONLY full edge pass ----------------
__global__ void k_bucket(const int* __restrict__ src, const int* __restrict__ dst, int E) {
    int t = blockIdx.x * blockDim.x + threadIdx.x;
    int base = t * 4;
    if (base + 3 < E) {
        int4 d4 = __ldg((const int4*)(dst + base));
        int4 s4 = __ldg((const int4*)(src + base));
        int p;
        p = atomicAdd(&g_deg[d4.x], 1); if (p < BCAP) g_bucket[(size_t)d4.x * BCAP + p] = s4.x;
        p = atomicAdd(&g_deg[d4.y], 1); if (p < BCAP) g_bucket[(size_t)d4.y * BCAP + p] = s4.y;
        p = atomicAdd(&g_deg[d4.z], 1); if (p < BCAP) g_bucket[(size_t)d4.z * BCAP + p] = s4.z;
        p = atomicAdd(&g_deg[d4.w], 1); if (p < BCAP) g_bucket[(size_t)d4.w * BCAP + p] = s4.w;
    } else {
        for (int e = base; e < E; e++) {
            int d = __ldg(&dst[e]), s = __ldg(&src[e]);
            int p = atomicAdd(&g_deg[d], 1);
            if (p < BCAP) g_bucket[(size_t)d * BCAP + p] = s;
        }
    }
}

// ---------------- t2: node-1 bucket -> B2/list2 (1 thread) ----------------
__global__ void k_t2() {
    if (threadIdx.x != 0) return;
    int n1 = min(g_deg[OUT_NODE], BCAP);
    int n2 = 0;
    const int* b = &g_bucket[(size_t)OUT_NODE * BCAP];
    for (int i = 0; i < n1; i++) {
        int s = b[i];
        unsigned m = 1u << (s & 31);
        unsigned old = atomicOr(&g_B2[s >> 5], m);
        if (!(old & m)) { g_list2[n2++] = s; zero64(&g_agg2[(size_t)s * 64]); }
    }
    g_cnt2 = n2;
}

// ---------------- t21: warp per B2 node -> e2, B1/list1 ----------------
__global__ void k_t21() {
    int n = g_cnt2;
    int lane = threadIdx.x & 31;
    int warp = (blockIdx.x * blockDim.x + threadIdx.x) >> 5;
    int nw = (gridDim.x * blockDim.x) >> 5;
    for (int i = warp; i < n; i += nw) {
        int v = g_list2[i];
        int dv = min(g_deg[v], BCAP);
        const int* b = &g_bucket[(size_t)v * BCAP];
        for (int j = lane; j < dv; j += 32) {
            int s = b[j];
            int p = atomicAdd(&g_e2n, 1);
            if (p < E2CAP) { g_e2s[p] = s; g_e2d[p] = v; }
            unsigned m = 1u << (s & 31);
            unsigned old = atomicOr(&g_B1[s >> 5], m);
            if (!(old & m)) {
                int q = atomicAdd(&g_cnt1, 1);
                g_list1[q] = s;
                zero64(&g_agg1[(size_t)s * 64]);
            }
        }
    }
}

// ---------------- t10: warp per B1 node -> eb, B0/list0 ----------------
__global__ void k_t10() {
    int n = g_cnt1;
    int lane = threadIdx.x & 31;
    int warp = (blockIdx.x * blockDim.x + threadIdx.x) >> 5;
    int nw = (gridDim.x * blockDim.x) >> 5;
    for (int i = warp; i < n; i += nw) {
        int v = g_list1[i];
        int dv = min(g_deg[v], BCAP);
        const int* b = &g_bucket[(size_t)v * BCAP];
        for (int j = lane; j < dv; j += 32) {
            int s = b[j];
            int p = atomicAdd(&g_ebn, 1);
            if (p < EBCAP) { g_ebs[p] = s; g_ebd[p] = v; }
            unsigned m = 1u << (s & 31);
            unsigned old = atomicOr(&g_B0[s >> 5], m);
            if (!(old & m)) {
                int q = atomicAdd(&g_cnt0, 1);
                g_list0[q] = s;
            }
        }
    }
}

// ---------------- agg0: warp per B0 node, bucket reduce ----------------
__global__ void k_agg0(const float* __restrict__ in_feat) {
    int n = g_cnt0;
    int lane = threadIdx.x & 31;
    int warp = (blockIdx.x * blockDim.x + threadIdx.x) >> 5;
    int nw = (gridDim.x * blockDim.x) >> 5;
    for (int i = warp; i < n; i += nw) {
        int v = g_list0[i];
        int dv = min(g_deg[v], BCAP);
        const int* b = &g_bucket[(size_t)v * BCAP];
        float sum = 0.f;
        for (int j = lane; j < dv; j += 32) sum += __ldg(&in_feat[b[j]]);
        #pragma unroll
        for (int o = 16; o; o >>= 1) sum += __shfl_down_sync(0xffffffffu, sum, o);
        if (lane == 0) g_agg0[v] = sum;
    }
}

// ---------------- agg1: agg1[d][:] += lrelu(agg0[s]*W0+b0), warp/edge -------
__global__ void k_agg1(const float* __restrict__ W0, const float* __restrict__ b0) {
    int n = min(g_ebn, EBCAP);
    int lane = threadIdx.x & 31;
    int warp = (blockIdx.x * blockDim.x + threadIdx.x) >> 5;
    int nw = (gridDim.x * blockDim.x) >> 5;
    float w0a = __ldg(&W0[lane]), w0b = __ldg(&W0[lane + 32]);
    float b0a = __ldg(&b0[lane]), b0b = __ldg(&b0[lane + 32]);
    for (int i = warp; i < n; i += nw) {
        int s = g_ebs[i], d = g_ebd[i];
        float a0 = g_agg0[s];
        float* a = &g_agg1[(size_t)d * 64];
        atomicAdd(&a[lane],      lrelu(fmaf(a0, w0a, b0a)));
        atomicAdd(&a[lane + 32], lrelu(fmaf(a0, w0b, b0b)));
    }
}

// ---------------- h1x2: per node in list1 (warp/node) ----------------
__global__ void k_h1x2(const float* __restrict__ W1, const float* __restrict__ b1,
                       const float* __restrict__ W2) {
    int n = g_cnt1;
    int lane = threadIdx.x & 31;
    int warp = (blockIdx.x * blockDim.x + threadIdx.x) >> 5;
    int nw = (gridDim.x * blockDim.x) >> 5;
    for (int i = warp; i < n; i += nw) {
        int v = g_list1[i];
        float a0 = g_agg1[(size_t)v * 64 + lane];
        float a1 = g_agg1[(size_t)v * 64 + lane + 32];
        float h0r = __ldg(&b1[lane]);
        float h1r = __ldg(&b1[lane + 32]);
        float h2r = __ldg(&b1[lane + 64]);
        float h3r = __ldg(&b1[lane + 96]);
        #pragma unroll
        for (int k = 0; k < 64; k++) {
            float ak = __shfl_sync(0xffffffffu, (k < 32) ? a0 : a1, k & 31);
            const float* wr = &W1[k * 128];
            h0r = fmaf(ak, __ldg(&wr[lane]),      h0r);
            h1r = fmaf(ak, __ldg(&wr[lane + 32]), h1r);
            h2r = fmaf(ak, __ldg(&wr[lane + 64]), h2r);
            h3r = fmaf(ak, __ldg(&wr[lane + 96]), h3r);
        }
        float h[4] = { lrelu(h0r), lrelu(h1r), lrelu(h2r), lrelu(h3r) };
        float x0 = 0.f, x1 = 0.f;
        #pragma unroll
        for (int k = 0; k < 128; k++) {
            float hk = __shfl_sync(0xffffffffu, h[k >> 5], k & 31);
            const float* wr = &W2[k * 64];
            x0 = fmaf(hk, __ldg(&wr[lane]),      x0);
            x1 = fmaf(hk, __ldg(&wr[lane + 32]), x1);
        }
        g_x2[(size_t)v * 64 + lane]      = x0;
        g_x2[(size_t)v * 64 + lane + 32] = x1;
    }
}

// ---------------- tail: agg2 + h2x3 + final + out + cleanup (1 block) -------
__global__ void __launch_bounds__(1024, 1)
k_tail(const float* __restrict__ b2, const float* __restrict__ W3,
       const float* __restrict__ b3, float* __restrict__ out) {
    int lane = threadIdx.x & 31;
    int bw = threadIdx.x >> 5;

    int n2 = min(g_e2n, E2CAP);
    for (int i = bw; i < n2; i += 32) {
        int s = g_e2s[i], d = g_e2d[i];
        float* a = &g_agg2[(size_t)d * 64];
        atomicAdd(&a[lane],      __ldcg(&g_x2[(size_t)s * 64 + lane]));
        atomicAdd(&a[lane + 32], __ldcg(&g_x2[(size_t)s * 64 + lane + 32]));
    }
    __syncthreads();

    int n3 = g_cnt2;
    for (int i = bw; i < n3; i += 32) {
        int v = g_list2[i];
        float ya = lrelu(__ldcg(&g_agg2[(size_t)v * 64 + lane])      + __ldg(&b2[lane]));
        float yb = lrelu(__ldcg(&g_agg2[(size_t)v * 64 + lane + 32]) + __ldg(&b2[lane + 32]));
        float p = fmaf(ya, __ldg(&W3[lane]), yb * __ldg(&W3[lane + 32]));
        #pragma unroll
        for (int o = 16; o; o >>= 1) p += __shfl_down_sync(0xffffffffu, p, o);
        if (lane == 0) g_x3[v] = p;
    }
    __syncthreads();

    // final: sum x3 over node-1's bucket (duplicate edges count correctly)
    __shared__ float red[32];
    int n1 = min(g_deg[OUT_NODE], BCAP);
    const int* b1b = &g_bucket[(size_t)OUT_NODE * BCAP];
    float s = 0.f;
    for (int i = threadIdx.x; i < n1; i += 1024) s += __ldcg(&g_x3[b1b[i]]);
    #pragma unroll
    for (int o = 16; o; o >>= 1) s += __shfl_down_sync(0xffffffffu, s, o);
    if (lane == 0) red[bw] = s;
    __syncthreads();
    if (threadIdx.x < 32) {
        float t = red[lane];
        #pragma unroll
        for (int o = 16; o; o >>= 1) t += __shfl_down_sync(0xffffffffu, t, o);
        if (lane == 0) out[0] = lrelu(t + __ldg(&b3[0]));
    }
    __syncthreads();

    // cleanup for next graph replay: deg (full), bitmaps (via lists), counters
    for (int i = threadIdx.x; i < MAXN; i += 1024) g_deg[i] = 0;
    int c2 = g_cnt2, c1 = g_cnt1, c0 = g_cnt0;
    for (int i = threadIdx.x; i < c2; i += 1024) { int v = g_list2[i]; g_B2[v >> 5] = 0u; }
    for (int i = threadIdx.x; i < c1; i += 1024) { int v = g_list1[i]; g_B1[v >> 5] = 0u; }
    for (int i = threadIdx.x; i < c0; i += 1024) { int v = g_list0[i]; g_B0[v >> 5] = 0u; }
    __syncthreads();
    if (threadIdx.x == 0) {
        g_cnt0 = 0; g_cnt1 = 0; g_cnt2 = 0; g_e2n = 0; g_ebn = 0;
        __threadfence();
    }
}

// ---------------------------------------------------------------------------
extern "C" void kernel_launch(void* const* d_in, const int* in_sizes, int n_in,
                              void* d_out, int out_size) {
    const float* in_feat = (const float*)d_in[0];
    const int*   src     = (const int*)  d_in[1];
    const int*   dst     = (const int*)  d_in[2];
    const float* W0 = (const float*)d_in[3];
    const float* b0 = (const float*)d_in[4];
    const float* W1 = (const float*)d_in[5];
    const float* b1 = (const float*)d_in[6];
    const float* W2 = (const float*)d_in[7];
    const float* b2 = (const float*)d_in[8];
    const float* W3 = (const float*)d_in[9];
    const float* b3 = (const float*)d_in[10];
    float* out = (float*)d_out;

    int E = in_sizes[1];
    int T = (E + 3) / 4;
    int bb = (T + 255) / 256;

    k_bucket<<<bb, 256>>>(src, dst, E);  // the ONLY full-edge pass
    k_t2<<<1, 32>>>();
    k_t21<<<1, 512>>>();
    k_t10<<<8, 256>>>();
    k_agg0<<<32, 256>>>(in_feat);
    k_agg1<<<128, 256>>>(W0, b0);
    k_h1x2<<<64, 256>>>(W1, b1, W2);
    k_tail<<<1, 1024>>>(b2, W3, b3, out);
}

// round 11
// speedup vs baseline: 3.1310x; 1.5699x over previous
#include <cuda_runtime.h>

// ---------------------------------------------------------------------------
// DummyGCN4: 4-layer GCN, output = h3[node 1] only.
// R11: backward-slice with a FORKED-STREAM graph.
//   Branch A (critical path): scan32 -> scan21 -> scan10 (pure eb capture)
//   Branch B (parallel):      agg0all — agg0[dst] += in_feat[src] for ALL
//                             edges; depends on nothing, overlaps branch A.
//   Join -> agg1 (h0 fused) -> h1x2 -> tail (agg2+h2x3+final+out).
//   B0 bitmap/list eliminated. Fork/join via events during stream capture
//   (they become graph dependencies; branches execute concurrently).
// ---------------------------------------------------------------------------

#define MAXN 50048
#define BMW  1568
#define OUT_NODE 1
#define E1CAP  8192       // node-1 in-edges (expect ~16)
#define E2CAP  32768      // edges into B2 (expect ~256)
#define EBCAP  262144     // edges into B1 (expect ~4k)

__device__ unsigned g_B1[BMW], g_B2[BMW];
__device__ int   g_list1[MAXN], g_list2[MAXN];
__device__ int   g_cnt1, g_cnt2;
__device__ int   g_e1s[E1CAP];                 __device__ int g_e1n;
__device__ int   g_e2s[E2CAP],  g_e2d[E2CAP];  __device__ int g_e2n;
__device__ int   g_ebs[EBCAP],  g_ebd[EBCAP];  __device__ int g_ebn;
__device__ float g_agg0[MAXN];
__device__ float g_agg1[(size_t)MAXN * 64];
__device__ float g_x2[(size_t)MAXN * 64];
__device__ float g_agg2[(size_t)MAXN * 64];
__device__ float g_x3[MAXN];

__device__ __forceinline__ float lrelu(float x) { return x >= 0.f ? x : 0.01f * x; }
__device__ __forceinline__ bool tb(const unsigned* b, int i) {
    return (b[i >> 5] >> (i & 31)) & 1u;
}
__device__ __forceinline__ void zero64(float* a) {
    float4 z = make_float4(0.f, 0.f, 0.f, 0.f);
    float4* a4 = (float4*)a;
    #pragma unroll
    for (int j = 0; j < 16; j++) a4[j] = z;
}

// ---------------- clear: agg0 + bitmaps + counters ----------------
__global__ void k_clear() {
    int t = blockIdx.x * blockDim.x + threadIdx.x;
    if (t < MAXN) g_agg0[t] = 0.f;
    if (t < BMW) { g_B1[t] = 0; g_B2[t] = 0; }
    if (t == 0) { g_cnt1 = 0; g_cnt2 = 0; g_e1n = 0; g_e2n = 0; g_ebn = 0; }
}

// ---------------- branch B: agg0 for ALL nodes (no deps) ----------------
__global__ void k_agg0all(const int* __restrict__ src, const int* __restrict__ dst,
                          const float* __restrict__ in_feat, int E) {
    int t = blockIdx.x * blockDim.x + threadIdx.x;
    int base = t * 4;
    if (base + 3 < E) {
        int4 d4 = *(const int4*)(dst + base);
        int4 s4 = *(const int4*)(src + base);
        atomicAdd(&g_agg0[d4.x], __ldg(&in_feat[s4.x]));
        atomicAdd(&g_agg0[d4.y], __ldg(&in_feat[s4.y]));
        atomicAdd(&g_agg0[d4.z], __ldg(&in_feat[s4.z]));
        atomicAdd(&g_agg0[d4.w], __ldg(&in_feat[s4.w]));
    } else {
        for (int e = base; e < E; e++)
            atomicAdd(&g_agg0[dst[e]], __ldg(&in_feat[src[e]]));
    }
}

// ---------------- scan32: dst == OUT_NODE ----------------
__device__ __forceinline__ void hit32(const int* __restrict__ src, int e) {
    int s = src[e];
    int p = atomicAdd(&g_e1n, 1);
    if (p < E1CAP) g_e1s[p] = s;
    unsigned m = 1u << (s & 31);
    unsigned old = atomicOr(&g_B2[s >> 5], m);
    if (!(old & m)) {
        int q = atomicAdd(&g_cnt2, 1);
        g_list2[q] = s;
        zero64(&g_agg2[(size_t)s * 64]);
    }
}
__global__ void k_scan32(const int* __restrict__ src, const int* __restrict__ dst, int E) {
    int t = blockIdx.x * blockDim.x + threadIdx.x;
    int base = t * 4;
    if (base + 3 < E) {
        int4 d4 = *(const int4*)(dst + base);
        if (d4.x == OUT_NODE) hit32(src, base + 0);
        if (d4.y == OUT_NODE) hit32(src, base + 1);
        if (d4.z == OUT_NODE) hit32(src, base + 2);
        if (d4.w == OUT_NODE) hit32(src, base + 3);
    } else {
        for (int e = base; e < E; e++) if (dst[e] == OUT_NODE) hit32(src, e);
    }
}

// ---------------- scan21: dst in B2 -> B1/list1/e2 ----------------
__device__ __forceinline__ void hit21(const int* __restrict__ src, int e, int d) {
    int s = src[e];
    int p = atomicAdd(&g_e2n, 1);
    if (p < E2CAP) { g_e2s[p] = s; g_e2d[p] = d; }
    unsigned m = 1u << (s & 31);
    unsigned old = atomicOr(&g_B1[s >> 5], m);
    if (!(old & m)) {
        int q = atomicAdd(&g_cnt1, 1);
        g_list1[q] = s;
        zero64(&g_agg1[(size_t)s * 64]);
    }
}
__global__ void k_scan21(const int* __restrict__ src, const int* __restrict__ dst, int E) {
    int t = blockIdx.x * blockDim.x + threadIdx.x;
    int base = t * 4;
    if (base + 3 < E) {
        int4 d4 = *(const int4*)(dst + base);
        if (tb(g_B2, d4.x)) hit21(src, base + 0, d4.x);
        if (tb(g_B2, d4.y)) hit21(src, base + 1, d4.y);
        if (tb(g_B2, d4.z)) hit21(src, base + 2, d4.z);
        if (tb(g_B2, d4.w)) hit21(src, base + 3, d4.w);
    } else {
        for (int e = base; e < E; e++) { int d = dst[e]; if (tb(g_B2, d)) hit21(src, e, d); }
    }
}

// ---------------- scan10: dst in B1 -> eb (pure capture, no bitmap) ---------
__global__ void k_scan10(const int* __restrict__ src, const int* __restrict__ dst, int E) {
    int t = blockIdx.x * blockDim.x + threadIdx.x;
    int base = t * 4;
    if (base + 3 < E) {
        int4 d4 = *(const int4*)(dst + base);
        #pragma unroll
        for (int i = 0; i < 4; i++) {
            int d = (i == 0) ? d4.x : (i == 1) ? d4.y : (i == 2) ? d4.z : d4.w;
            if (tb(g_B1, d)) {
                int p = atomicAdd(&g_ebn, 1);
                if (p < EBCAP) { g_ebs[p] = src[base + i]; g_ebd[p] = d; }
            }
        }
    } else {
        for (int e = base; e < E; e++) {
            int d = dst[e];
            if (tb(g_B1, d)) {
                int p = atomicAdd(&g_ebn, 1);
                if (p < EBCAP) { g_ebs[p] = src[e]; g_ebd[p] = d; }
            }
        }
    }
}

// ---------------- agg1: agg1[d][:] += lrelu(agg0[s]*W0+b0), warp/edge -------
__global__ void k_agg1(const float* __restrict__ W0, const float* __restrict__ b0) {
    int n = min(g_ebn, EBCAP);
    int lane = threadIdx.x & 31;
    int warp = (blockIdx.x * blockDim.x + threadIdx.x) >> 5;
    int nw = (gridDim.x * blockDim.x) >> 5;
    float w0a = __ldg(&W0[lane]), w0b = __ldg(&W0[lane + 32]);
    float b0a = __ldg(&b0[lane]), b0b = __ldg(&b0[lane + 32]);
    for (int i = warp; i < n; i += nw) {
        int s = g_ebs[i], d = g_ebd[i];
        float a0 = g_agg0[s];
        float* a = &g_agg1[(size_t)d * 64];
        atomicAdd(&a[lane],      lrelu(fmaf(a0, w0a, b0a)));
        atomicAdd(&a[lane + 32], lrelu(fmaf(a0, w0b, b0b)));
    }
}

// ---------------- h1x2: per node in list1 (warp/node) ----------------
__global__ void k_h1x2(const float* __restrict__ W1, const float* __restrict__ b1,
                       const float* __restrict__ W2) {
    int n = g_cnt1;
    int lane = threadIdx.x & 31;
    int warp = (blockIdx.x * blockDim.x + threadIdx.x) >> 5;
    int nw = (gridDim.x * blockDim.x) >> 5;
    for (int i = warp; i < n; i += nw) {
        int v = g_list1[i];
        float a0 = g_agg1[(size_t)v * 64 + lane];
        float a1 = g_agg1[(size_t)v * 64 + lane + 32];
        float h0r = __ldg(&b1[lane]);
        float h1r = __ldg(&b1[lane + 32]);
        float h2r = __ldg(&b1[lane + 64]);
        float h3r = __ldg(&b1[lane + 96]);
        #pragma unroll
        for (int k = 0; k < 64; k++) {
            float ak = __shfl_sync(0xffffffffu, (k < 32) ? a0 : a1, k & 31);
            const float* wr = &W1[k * 128];
            h0r = fmaf(ak, __ldg(&wr[lane]),      h0r);
            h1r = fmaf(ak, __ldg(&wr[lane + 32]), h1r);
            h2r = fmaf(ak, __ldg(&wr[lane + 64]), h2r);
            h3r = fmaf(ak, __ldg(&wr[lane + 96]), h3r);
        }
        float h[4] = { lrelu(h0r), lrelu(h1r), lrelu(h2r), lrelu(h3r) };
        float x0 = 0.f, x1 = 0.f;
        #pragma unroll
        for (int k = 0; k < 128; k++) {
            float hk = __shfl_sync(0xffffffffu, h[k >> 5], k & 31);
            const float* wr = &W2[k * 64];
            x0 = fmaf(hk, __ldg(&wr[lane]),      x0);
            x1 = fmaf(hk, __ldg(&wr[lane + 32]), x1);
        }
        g_x2[(size_t)v * 64 + lane]      = x0;
        g_x2[(size_t)v * 64 + lane + 32] = x1;
    }
}

// ---------------- tail: agg2 + h2x3 + final + out (1 block) ----------------
__global__ void __launch_bounds__(1024, 1)
k_tail(const float* __restrict__ b2, const float* __restrict__ W3,
       const float* __restrict__ b3, float* __restrict__ out) {
    int lane = threadIdx.x & 31;
    int bw = threadIdx.x >> 5;

    int n2 = min(g_e2n, E2CAP);
    for (int i = bw; i < n2; i += 32) {
        int s = g_e2s[i], d = g_e2d[i];
        float* a = &g_agg2[(size_t)d * 64];
        atomicAdd(&a[lane],      __ldcg(&g_x2[(size_t)s * 64 + lane]));
        atomicAdd(&a[lane + 32], __ldcg(&g_x2[(size_t)s * 64 + lane + 32]));
    }
    __syncthreads();

    int n3 = g_cnt2;
    for (int i = bw; i < n3; i += 32) {
        int v = g_list2[i];
        float ya = lrelu(__ldcg(&g_agg2[(size_t)v * 64 + lane])      + __ldg(&b2[lane]));
        float yb = lrelu(__ldcg(&g_agg2[(size_t)v * 64 + lane + 32]) + __ldg(&b2[lane + 32]));
        float p = fmaf(ya, __ldg(&W3[lane]), yb * __ldg(&W3[lane + 32]));
        #pragma unroll
        for (int o = 16; o; o >>= 1) p += __shfl_down_sync(0xffffffffu, p, o);
        if (lane == 0) g_x3[v] = p;
    }
    __syncthreads();

    __shared__ float red[32];
    int n1 = min(g_e1n, E1CAP);
    float s = 0.f;
    for (int i = threadIdx.x; i < n1; i += 1024) s += __ldcg(&g_x3[g_e1s[i]]);
    #pragma unroll
    for (int o = 16; o; o >>= 1) s += __shfl_down_sync(0xffffffffu, s, o);
    if (lane == 0) red[bw] = s;
    __syncthreads();
    if (threadIdx.x < 32) {
        float t = red[lane];
        #pragma unroll
        for (int o = 16; o; o >>= 1) t += __shfl_down_sync(0xffffffffu, t, o);
        if (lane == 0) out[0] = lrelu(t + __ldg(&b3[0]));
    }
}

// ---------------------------------------------------------------------------
extern "C" void kernel_launch(void* const* d_in, const int* in_sizes, int n_in,
                              void* d_out, int out_size) {
    const float* in_feat = (const float*)d_in[0];
    const int*   src     = (const int*)  d_in[1];
    const int*   dst     = (const int*)  d_in[2];
    const float* W0 = (const float*)d_in[3];
    const float* b0 = (const float*)d_in[4];
    const float* W1 = (const float*)d_in[5];
    const float* b1 = (const float*)d_in[6];
    const float* W2 = (const float*)d_in[7];
    const float* b2 = (const float*)d_in[8];
    const float* W3 = (const float*)d_in[9];
    const float* b3 = (const float*)d_in[10];
    float* out = (float*)d_out;

    int E = in_sizes[1];
    int T = (E + 3) / 4;
    int sb = (T + 255) / 256;            // ~782 blocks per full scan
    int cb = (MAXN + 255) / 256;

    // host objects created once (outside capture on the correctness call);
    // every call issues the IDENTICAL launch/fork sequence.
    static cudaStream_t s2 = nullptr;
    static cudaEvent_t evF = nullptr, evJ = nullptr;
    if (!s2) {
        cudaStreamCreateWithFlags(&s2, cudaStreamNonBlocking);
        cudaEventCreateWithFlags(&evF, cudaEventDisableTiming);
        cudaEventCreateWithFlags(&evJ, cudaEventDisableTiming);
    }

    k_clear<<<cb, 256>>>();

    // fork: branch B (agg0all) runs concurrently with the scan chain
    cudaEventRecord(evF, 0);
    cudaStreamWaitEvent(s2, evF, 0);
    k_agg0all<<<sb, 256, 0, s2>>>(src, dst, in_feat, E);
    cudaEventRecord(evJ, s2);

    // branch A: backward-slice scan chain (critical path)
    k_scan32<<<sb, 256>>>(src, dst, E);
    k_scan21<<<sb, 256>>>(src, dst, E);
    k_scan10<<<sb, 256>>>(src, dst, E);

    // join: agg1 needs both eb (A) and agg0 (B)
    cudaStreamWaitEvent(0, evJ, 0);
    k_agg1<<<128, 256>>>(W0, b0);
    k_h1x2<<<64, 256>>>(W1, b1, W2);
    k_tail<<<1, 1024>>>(b2, W3, b3, out);
}